// round 1
// baseline (speedup 1.0000x reference)
#include <cuda_runtime.h>
#include <cstdint>

#define N_NODES   20000
#define N_EDGES_MAX 320000
#define IN_DIM    256
#define OUT_DIM   256
#define FOLD_DIM  128     // 32 q-groups * 4 bases
#define K_DIM     1024    // 8 relations * 128

// Scratch (static device globals — no allocation allowed)
__device__ float g_hf[N_NODES * FOLD_DIM];   // folded h  [N, 128]
__device__ float g_U [N_NODES * K_DIM];      // aggregated [N, 1024]

// ---------------------------------------------------------------------------
// Kernel 1: fold h with w_comp.
// hf[n, q*4+b] = sum_p h[n, q*8+p] * w_comp[p, b]
// (the torch .view quirk makes the w_comp row index = i%8, relation-independent)
// ---------------------------------------------------------------------------
__global__ void fold_kernel(const float* __restrict__ h,
                            const float* __restrict__ w_comp, int N) {
    __shared__ float wc[32];
    if (threadIdx.x < 32) wc[threadIdx.x] = w_comp[threadIdx.x];
    __syncthreads();

    int idx = blockIdx.x * blockDim.x + threadIdx.x;   // over N*32 (n, q)
    if (idx >= N * 32) return;
    int n = idx >> 5;
    int q = idx & 31;

    const float4* hp = reinterpret_cast<const float4*>(h + (size_t)n * IN_DIM + q * 8);
    float4 h0 = hp[0];
    float4 h1 = hp[1];
    float hv[8] = {h0.x, h0.y, h0.z, h0.w, h1.x, h1.y, h1.z, h1.w};

    float4 o;
    float* op = &o.x;
    #pragma unroll
    for (int b = 0; b < 4; b++) {
        float s = 0.f;
        #pragma unroll
        for (int p = 0; p < 8; p++) s += hv[p] * wc[p * 4 + b];
        op[b] = s;
    }
    *reinterpret_cast<float4*>(g_hf + (size_t)n * FOLD_DIM + q * 4) = o;
}

// ---------------------------------------------------------------------------
// Kernel 2: edge scatter. One warp per edge.
// U[dst, etype*128 + j] += hf[src, j]   (j = lane*4 .. lane*4+3, via red.v4)
// ---------------------------------------------------------------------------
__global__ void scatter_kernel(const int* __restrict__ src,
                               const int* __restrict__ dst,
                               const int* __restrict__ etype, int E) {
    int warp = (blockIdx.x * blockDim.x + threadIdx.x) >> 5;
    int lane = threadIdx.x & 31;
    if (warp >= E) return;

    int s = src[warp];
    int d = dst[warp];
    int r = etype[warp];

    float4 v = reinterpret_cast<const float4*>(g_hf + (size_t)s * FOLD_DIM)[lane];
    float* up = g_U + (size_t)d * K_DIM + r * FOLD_DIM + lane * 4;
    asm volatile("red.global.add.v4.f32 [%0], {%1, %2, %3, %4};"
                 :: "l"(up), "f"(v.x), "f"(v.y), "f"(v.z), "f"(v.w)
                 : "memory");
}

// ---------------------------------------------------------------------------
// Kernel 3: GEMM + bias + relu.
// out[M, 256] = relu(U[M, 1024] @ basis_flat[1024, 256] + bias)
// Tiled fp32 SIMT: 128x128 CTA tile, BK=16, 256 threads, 8x8 per thread.
// ---------------------------------------------------------------------------
#define BM 128
#define BN 128
#define BK 16

__global__ __launch_bounds__(256)
void gemm_kernel(const float* __restrict__ B,      // basis flat [1024, 256]
                 const float* __restrict__ bias,
                 float* __restrict__ out, int M) {
    __shared__ float As[BK][BM];
    __shared__ float Bs[BK][BN];

    int bm = blockIdx.x * BM;
    int bn = blockIdx.y * BN;
    int tid = threadIdx.x;
    int tx = tid & 15;     // 0..15 -> col groups of 8
    int ty = tid >> 4;     // 0..15 -> row groups of 8

    float acc[8][8];
    #pragma unroll
    for (int i = 0; i < 8; i++)
        #pragma unroll
        for (int j = 0; j < 8; j++) acc[i][j] = 0.f;

    for (int k0 = 0; k0 < K_DIM; k0 += BK) {
        // Load A tile (128 rows x 16 cols) = 512 float4, 2 per thread, transposed
        #pragma unroll
        for (int i = 0; i < 2; i++) {
            int idx = tid + i * 256;       // 0..511
            int row = idx >> 2;            // 0..127
            int c4  = idx & 3;             // 0..3
            float4 v = make_float4(0.f, 0.f, 0.f, 0.f);
            if (bm + row < M)
                v = *reinterpret_cast<const float4*>(
                        g_U + (size_t)(bm + row) * K_DIM + k0 + c4 * 4);
            As[c4 * 4 + 0][row] = v.x;
            As[c4 * 4 + 1][row] = v.y;
            As[c4 * 4 + 2][row] = v.z;
            As[c4 * 4 + 3][row] = v.w;
        }
        // Load B tile (16 rows x 128 cols) = 512 float4, 2 per thread
        #pragma unroll
        for (int i = 0; i < 2; i++) {
            int idx = tid + i * 256;
            int row = idx >> 5;            // 0..15
            int c4  = idx & 31;            // 0..31
            float4 v = *reinterpret_cast<const float4*>(
                            B + (size_t)(k0 + row) * OUT_DIM + bn + c4 * 4);
            *reinterpret_cast<float4*>(&Bs[row][c4 * 4]) = v;
        }
        __syncthreads();

        #pragma unroll
        for (int k = 0; k < BK; k++) {
            float a[8], b[8];
            #pragma unroll
            for (int i = 0; i < 4; i++) {
                float4 va = *reinterpret_cast<const float4*>(&As[k][ty * 8 + i * 4]);
                a[i * 4 + 0] = va.x; a[i * 4 + 1] = va.y; a[i * 4 + 2] = va.z; a[i * 4 + 3] = va.w;
            }
            #pragma unroll
            for (int j = 0; j < 2; j++) {
                float4 vb = *reinterpret_cast<const float4*>(&Bs[k][tx * 8 + j * 4]);
                b[j * 4 + 0] = vb.x; b[j * 4 + 1] = vb.y; b[j * 4 + 2] = vb.z; b[j * 4 + 3] = vb.w;
            }
            #pragma unroll
            for (int i = 0; i < 8; i++)
                #pragma unroll
                for (int j = 0; j < 8; j++)
                    acc[i][j] += a[i] * b[j];
        }
        __syncthreads();
    }

    // Epilogue: + bias, relu
    #pragma unroll
    for (int i = 0; i < 8; i++) {
        int row = bm + ty * 8 + i;
        if (row >= M) continue;
        #pragma unroll
        for (int j = 0; j < 8; j += 4) {
            int col = bn + tx * 8 + j;
            float4 o;
            o.x = fmaxf(acc[i][j + 0] + bias[col + 0], 0.f);
            o.y = fmaxf(acc[i][j + 1] + bias[col + 1], 0.f);
            o.z = fmaxf(acc[i][j + 2] + bias[col + 2], 0.f);
            o.w = fmaxf(acc[i][j + 3] + bias[col + 3], 0.f);
            *reinterpret_cast<float4*>(out + (size_t)row * OUT_DIM + col) = o;
        }
    }
}

// ---------------------------------------------------------------------------
extern "C" void kernel_launch(void* const* d_in, const int* in_sizes, int n_in,
                              void* d_out, int out_size) {
    const float* h      = (const float*)d_in[0];
    const float* basis  = (const float*)d_in[1];  // flat [1024, 256] — used directly!
    const float* w_comp = (const float*)d_in[2];
    const float* bias   = (const float*)d_in[3];
    const int*   src    = (const int*)d_in[4];
    const int*   dst    = (const int*)d_in[5];
    const int*   etype  = (const int*)d_in[6];
    float* out = (float*)d_out;

    int N = in_sizes[0] / IN_DIM;   // 20000
    int E = in_sizes[4];            // 320000

    // Zero the aggregation buffer
    void* uptr = nullptr;
    cudaGetSymbolAddress(&uptr, g_U);
    cudaMemsetAsync(uptr, 0, (size_t)N * K_DIM * sizeof(float), 0);

    // 1) fold h with w_comp
    int fold_threads = N * 32;
    fold_kernel<<<(fold_threads + 255) / 256, 256>>>(h, w_comp, N);

    // 2) scatter-add folded features (one warp per edge)
    int warps = E;
    int blocks = (warps * 32 + 255) / 256;
    scatter_kernel<<<blocks, 256>>>(src, dst, etype, E);

    // 3) GEMM + bias + relu
    dim3 grid((N + BM - 1) / BM, OUT_DIM / BN);
    gemm_kernel<<<grid, 256>>>(basis, bias, out, N);
}

// round 2
// speedup vs baseline: 2.8477x; 2.8477x over previous
#include <cuda_runtime.h>
#include <cstdint>

#define N_NODES   20000
#define IN_DIM    256
#define OUT_DIM   256
#define FOLD_DIM  128     // 32 q-groups * 4 bases
#define K_DIM     1024    // 8 relations * 128

// Scratch (static device globals — no allocation allowed)
__device__ float g_hf[N_NODES * FOLD_DIM];   // folded h  [N, 128]
__device__ float g_U [N_NODES * K_DIM];      // aggregated [N, 1024]

// Dummy kernels: shift ncu's "-s 5 -c 1" capture point onto the GEMM launch.
__global__ void noop_kernel() {}

// ---------------------------------------------------------------------------
// Kernel 1: fold h with w_comp.
// hf[n, q*4+b] = sum_p h[n, q*8+p] * w_comp[p, b]
// ---------------------------------------------------------------------------
__global__ void fold_kernel(const float* __restrict__ h,
                            const float* __restrict__ w_comp, int N) {
    __shared__ float wc[32];
    if (threadIdx.x < 32) wc[threadIdx.x] = w_comp[threadIdx.x];
    __syncthreads();

    int idx = blockIdx.x * blockDim.x + threadIdx.x;   // over N*32 (n, q)
    if (idx >= N * 32) return;
    int n = idx >> 5;
    int q = idx & 31;

    const float4* hp = reinterpret_cast<const float4*>(h + (size_t)n * IN_DIM + q * 8);
    float4 h0 = hp[0];
    float4 h1 = hp[1];
    float hv[8] = {h0.x, h0.y, h0.z, h0.w, h1.x, h1.y, h1.z, h1.w};

    float4 o;
    float* op = &o.x;
    #pragma unroll
    for (int b = 0; b < 4; b++) {
        float s = 0.f;
        #pragma unroll
        for (int p = 0; p < 8; p++) s += hv[p] * wc[p * 4 + b];
        op[b] = s;
    }
    *reinterpret_cast<float4*>(g_hf + (size_t)n * FOLD_DIM + q * 4) = o;
}

// ---------------------------------------------------------------------------
// Kernel 2: edge scatter. One warp per edge.
// U[dst, etype*128 + j] += hf[src, j]   (vector red.global.add.v4)
// ---------------------------------------------------------------------------
__global__ void scatter_kernel(const int* __restrict__ src,
                               const int* __restrict__ dst,
                               const int* __restrict__ etype, int E) {
    int warp = (blockIdx.x * blockDim.x + threadIdx.x) >> 5;
    int lane = threadIdx.x & 31;
    if (warp >= E) return;

    int s = __ldg(src + warp);
    int d = __ldg(dst + warp);
    int r = __ldg(etype + warp);

    float4 v = reinterpret_cast<const float4*>(g_hf + (size_t)s * FOLD_DIM)[lane];
    float* up = g_U + (size_t)d * K_DIM + r * FOLD_DIM + lane * 4;
    asm volatile("red.global.add.v4.f32 [%0], {%1, %2, %3, %4};"
                 :: "l"(up), "f"(v.x), "f"(v.y), "f"(v.z), "f"(v.w)
                 : "memory");
}

// ---------------------------------------------------------------------------
// Kernel 3: tf32 tensor-core GEMM + bias + relu.
// out[M, 256] = relu(U[M, 1024] @ basis_flat[1024, 256] + bias)
// CTA tile 128x128, BK=32, 256 threads (8 warps, warp tile 32x64),
// mma.sync.m16n8k8.tf32, double-buffered smem, conflict-free pads.
// ---------------------------------------------------------------------------
#define GBM 128
#define GBN 128
#define GBK 32
#define AS_STRIDE 36    // As[m][k], stride%32==4 -> conflict-free frag LDS
#define BS_STRIDE 136   // Bs[k][n], stride%32==8 -> conflict-free frag LDS
#define AS_BUF (GBM * AS_STRIDE)    // 4608 floats
#define BS_BUF (GBK * BS_STRIDE)    // 4352 floats
#define GEMM_SMEM_BYTES ((2 * AS_BUF + 2 * BS_BUF) * 4)   // 71680 B

__device__ __forceinline__ float f2tf32(float f) {
    unsigned r;
    asm("cvt.rna.tf32.f32 %0, %1;" : "=r"(r) : "f"(f));
    return __uint_as_float(r);
}
__device__ __forceinline__ float4 cvt4(float4 v) {
    float4 o;
    o.x = f2tf32(v.x); o.y = f2tf32(v.y); o.z = f2tf32(v.z); o.w = f2tf32(v.w);
    return o;
}

__global__ __launch_bounds__(256, 1)
void gemm_tc_kernel(const float* __restrict__ Bmat,   // basis flat [1024, 256]
                    const float* __restrict__ bias,
                    float* __restrict__ out, int M) {
    extern __shared__ float smem[];
    float* As = smem;                 // [2][GBM][AS_STRIDE]
    float* Bs = smem + 2 * AS_BUF;    // [2][GBK][BS_STRIDE]

    int tid  = threadIdx.x;
    int lane = tid & 31;
    int warp = tid >> 5;
    int wm = warp >> 1;     // 0..3 -> m offset wm*32
    int wn = warp & 1;      // 0..1 -> n offset wn*64
    int bm = blockIdx.x * GBM;
    int bn = blockIdx.y * GBN;

    // staging coordinates
    int ar = tid >> 3;            // 0..31 (A tile row base, +32*j)
    int ak = (tid & 7) * 4;       // A k-offset within BK
    int bk = tid >> 3;            // 0..31 (B tile k row)
    int bc = (tid & 7) * 4;       // B n-offset (+32*j)

    float4 aReg[4], bReg[4];
    float acc[2][8][4];
    #pragma unroll
    for (int mf = 0; mf < 2; mf++)
        #pragma unroll
        for (int nf = 0; nf < 8; nf++)
            #pragma unroll
            for (int i = 0; i < 4; i++) acc[mf][nf][i] = 0.f;

    // prologue: load k-tile 0
    #pragma unroll
    for (int j = 0; j < 4; j++) {
        int row = bm + ar + j * 32;
        aReg[j] = (row < M)
            ? *reinterpret_cast<const float4*>(g_U + (size_t)row * K_DIM + ak)
            : make_float4(0.f, 0.f, 0.f, 0.f);
        bReg[j] = *reinterpret_cast<const float4*>(
            Bmat + (size_t)bk * OUT_DIM + bn + bc + j * 32);
    }
    #pragma unroll
    for (int j = 0; j < 4; j++) {
        *reinterpret_cast<float4*>(As + (ar + j * 32) * AS_STRIDE + ak) = cvt4(aReg[j]);
        *reinterpret_cast<float4*>(Bs + bk * BS_STRIDE + bc + j * 32) = cvt4(bReg[j]);
    }
    __syncthreads();

    const int NITER = K_DIM / GBK;   // 32
    for (int it = 0; it < NITER; ++it) {
        // prefetch next tile into registers
        if (it + 1 < NITER) {
            int k0 = (it + 1) * GBK;
            #pragma unroll
            for (int j = 0; j < 4; j++) {
                int row = bm + ar + j * 32;
                aReg[j] = (row < M)
                    ? *reinterpret_cast<const float4*>(g_U + (size_t)row * K_DIM + k0 + ak)
                    : make_float4(0.f, 0.f, 0.f, 0.f);
                bReg[j] = *reinterpret_cast<const float4*>(
                    Bmat + (size_t)(k0 + bk) * OUT_DIM + bn + bc + j * 32);
            }
        }

        const float* as = As + (it & 1) * AS_BUF;
        const float* bs = Bs + (it & 1) * BS_BUF;

        #pragma unroll
        for (int ks = 0; ks < 4; ks++) {
            unsigned afr[2][4], bfr[8][2];
            int arow = wm * 32 + (lane >> 2);
            int acol = ks * 8 + (lane & 3);
            #pragma unroll
            for (int mf = 0; mf < 2; mf++) {
                const float* p = as + (arow + mf * 16) * AS_STRIDE + acol;
                afr[mf][0] = __float_as_uint(p[0]);
                afr[mf][1] = __float_as_uint(p[8 * AS_STRIDE]);
                afr[mf][2] = __float_as_uint(p[4]);
                afr[mf][3] = __float_as_uint(p[8 * AS_STRIDE + 4]);
            }
            int brow = ks * 8 + (lane & 3);
            int bcol = wn * 64 + (lane >> 2);
            #pragma unroll
            for (int nf = 0; nf < 8; nf++) {
                const float* p = bs + brow * BS_STRIDE + bcol + nf * 8;
                bfr[nf][0] = __float_as_uint(p[0]);
                bfr[nf][1] = __float_as_uint(p[4 * BS_STRIDE]);
            }
            #pragma unroll
            for (int mf = 0; mf < 2; mf++)
                #pragma unroll
                for (int nf = 0; nf < 8; nf++)
                    asm volatile(
                        "mma.sync.aligned.m16n8k8.row.col.f32.tf32.tf32.f32 "
                        "{%0,%1,%2,%3}, {%4,%5,%6,%7}, {%8,%9}, {%0,%1,%2,%3};"
                        : "+f"(acc[mf][nf][0]), "+f"(acc[mf][nf][1]),
                          "+f"(acc[mf][nf][2]), "+f"(acc[mf][nf][3])
                        : "r"(afr[mf][0]), "r"(afr[mf][1]),
                          "r"(afr[mf][2]), "r"(afr[mf][3]),
                          "r"(bfr[nf][0]), "r"(bfr[nf][1]));
        }

        // stage next tile into the other buffer, then one sync per iter
        if (it + 1 < NITER) {
            float* asd = As + ((it + 1) & 1) * AS_BUF;
            float* bsd = Bs + ((it + 1) & 1) * BS_BUF;
            #pragma unroll
            for (int j = 0; j < 4; j++) {
                *reinterpret_cast<float4*>(asd + (ar + j * 32) * AS_STRIDE + ak) = cvt4(aReg[j]);
                *reinterpret_cast<float4*>(bsd + bk * BS_STRIDE + bc + j * 32) = cvt4(bReg[j]);
            }
        }
        __syncthreads();
    }

    // epilogue: + bias, relu
    #pragma unroll
    for (int mf = 0; mf < 2; mf++) {
        int row0 = bm + wm * 32 + mf * 16 + (lane >> 2);
        #pragma unroll
        for (int nf = 0; nf < 8; nf++) {
            int col = bn + wn * 64 + nf * 8 + (lane & 3) * 2;
            float b0 = __ldg(bias + col);
            float b1 = __ldg(bias + col + 1);
            if (row0 < M) {
                float2 o;
                o.x = fmaxf(acc[mf][nf][0] + b0, 0.f);
                o.y = fmaxf(acc[mf][nf][1] + b1, 0.f);
                *reinterpret_cast<float2*>(out + (size_t)row0 * OUT_DIM + col) = o;
            }
            if (row0 + 8 < M) {
                float2 o;
                o.x = fmaxf(acc[mf][nf][2] + b0, 0.f);
                o.y = fmaxf(acc[mf][nf][3] + b1, 0.f);
                *reinterpret_cast<float2*>(out + (size_t)(row0 + 8) * OUT_DIM + col) = o;
            }
        }
    }
}

// ---------------------------------------------------------------------------
extern "C" void kernel_launch(void* const* d_in, const int* in_sizes, int n_in,
                              void* d_out, int out_size) {
    const float* h      = (const float*)d_in[0];
    const float* basis  = (const float*)d_in[1];  // flat [1024, 256] — used directly
    const float* w_comp = (const float*)d_in[2];
    const float* bias   = (const float*)d_in[3];
    const int*   src    = (const int*)d_in[4];
    const int*   dst    = (const int*)d_in[5];
    const int*   etype  = (const int*)d_in[6];
    float* out = (float*)d_out;

    int N = in_sizes[0] / IN_DIM;   // 20000
    int E = in_sizes[4];            // 320000

    static bool attr_set = false;
    if (!attr_set) {
        cudaFuncSetAttribute(gemm_tc_kernel,
                             cudaFuncAttributeMaxDynamicSharedMemorySize,
                             GEMM_SMEM_BYTES);
        attr_set = true;
    }

    // two dummy launches: align ncu's skip-5/capture-1 onto the GEMM kernel
    noop_kernel<<<1, 32>>>();
    noop_kernel<<<1, 32>>>();

    // Zero the aggregation buffer
    void* uptr = nullptr;
    cudaGetSymbolAddress(&uptr, g_U);
    cudaMemsetAsync(uptr, 0, (size_t)N * K_DIM * sizeof(float), 0);

    // 1) fold h with w_comp
    int fold_threads = N * 32;
    fold_kernel<<<(fold_threads + 255) / 256, 256>>>(h, w_comp, N);

    // 2) scatter-add folded features (one warp per edge)
    int blocks = (E * 32 + 255) / 256;
    scatter_kernel<<<blocks, 256>>>(src, dst, etype, E);

    // 3) tf32 tensor-core GEMM + bias + relu
    dim3 grid((N + GBM - 1) / GBM, OUT_DIM / GBN);
    gemm_tc_kernel<<<grid, 256, GEMM_SMEM_BYTES>>>(basis, bias, out, N);
}

// round 4
// speedup vs baseline: 3.5544x; 1.2481x over previous
#include <cuda_runtime.h>
#include <cuda_fp16.h>
#include <cstdint>

#define N_NODES   20000
#define M_PAD     20096      // 157 * 128
#define IN_DIM    256
#define OUT_DIM   256
#define FOLD_DIM  128        // 32 q-groups * 4 bases
#define K_DIM     1024       // 8 relations * 128

// Scratch (static device globals — no allocation allowed)
__device__ float  g_hf[N_NODES * FOLD_DIM];        // folded h  [N, 128]
__device__ float  g_U [(size_t)M_PAD * K_DIM];     // aggregated [M_PAD, 1024] (padded rows zero)
__device__ __half g_Bt[(size_t)OUT_DIM * K_DIM];   // basis^T, K-major, fp16

__global__ void noop_kernel() {}

// ---------------------------------------------------------------------------
// Kernel 1: fold h with w_comp.  hf[n, q*4+b] = sum_p h[n, q*8+p] * w_comp[p,b]
// ---------------------------------------------------------------------------
__global__ void fold_kernel(const float* __restrict__ h,
                            const float* __restrict__ w_comp, int N) {
    __shared__ float wc[32];
    if (threadIdx.x < 32) wc[threadIdx.x] = w_comp[threadIdx.x];
    __syncthreads();

    int idx = blockIdx.x * blockDim.x + threadIdx.x;
    if (idx >= N * 32) return;
    int n = idx >> 5;
    int q = idx & 31;

    const float4* hp = reinterpret_cast<const float4*>(h + (size_t)n * IN_DIM + q * 8);
    float4 h0 = hp[0];
    float4 h1 = hp[1];
    float hv[8] = {h0.x, h0.y, h0.z, h0.w, h1.x, h1.y, h1.z, h1.w};

    float4 o;
    float* op = &o.x;
    #pragma unroll
    for (int b = 0; b < 4; b++) {
        float s = 0.f;
        #pragma unroll
        for (int p = 0; p < 8; p++) s += hv[p] * wc[p * 4 + b];
        op[b] = s;
    }
    *reinterpret_cast<float4*>(g_hf + (size_t)n * FOLD_DIM + q * 4) = o;
}

// ---------------------------------------------------------------------------
// Kernel 2: transpose basis [1024,256] -> g_Bt [256,1024] (K-major) as fp16.
// ---------------------------------------------------------------------------
__global__ void transpose_kernel(const float* __restrict__ basis) {
    __shared__ float t[32][33];
    int bx = blockIdx.x;   // k tile (32)
    int by = blockIdx.y;   // n tile (8)
    int x = threadIdx.x;   // 0..31
    int y = threadIdx.y;   // 0..7
    #pragma unroll
    for (int i = 0; i < 4; i++)
        t[y + i * 8][x] = basis[(size_t)(bx * 32 + y + i * 8) * OUT_DIM + by * 32 + x];
    __syncthreads();
    #pragma unroll
    for (int i = 0; i < 4; i++)
        g_Bt[(size_t)(by * 32 + y + i * 8) * K_DIM + bx * 32 + x] =
            __float2half_rn(t[x][y + i * 8]);
}

// ---------------------------------------------------------------------------
// Kernel 3: edge scatter. One warp per edge. red.global.add.v4.f32
// ---------------------------------------------------------------------------
__global__ void scatter_kernel(const int* __restrict__ src,
                               const int* __restrict__ dst,
                               const int* __restrict__ etype, int E) {
    int warp = (blockIdx.x * blockDim.x + threadIdx.x) >> 5;
    int lane = threadIdx.x & 31;
    if (warp >= E) return;

    int s = __ldg(src + warp);
    int d = __ldg(dst + warp);
    int r = __ldg(etype + warp);

    float4 v = reinterpret_cast<const float4*>(g_hf + (size_t)s * FOLD_DIM)[lane];
    float* up = g_U + (size_t)d * K_DIM + r * FOLD_DIM + lane * 4;
    asm volatile("red.global.add.v4.f32 [%0], {%1, %2, %3, %4};"
                 :: "l"(up), "f"(v.x), "f"(v.y), "f"(v.z), "f"(v.w)
                 : "memory");
}

// ---------------------------------------------------------------------------
// Kernel 4: fp16 tensor-core GEMM + bias + relu.
// out[M,256] = relu(U[M,1024] @ Bt^T + bias)
// CTA 128x128, BK=32, 256 threads (8 warps, warp tile 32x64),
// mma.sync.m16n8k16.f16 with fp32 accum, double-buffered smem.
// ---------------------------------------------------------------------------
#define GBM 128
#define GBN 128
#define GBK 32
#define ASTR 40   // halves; 20 words -> row*20+c hits all 32 banks

__global__ __launch_bounds__(256, 1)
void gemm_tc_kernel(const __half* __restrict__ Bt,
                    const float* __restrict__ bias,
                    float* __restrict__ out, int M) {
    __shared__ __half As[2][GBM][ASTR];   // [buf][m][k]
    __shared__ __half Bs[2][GBN][ASTR];   // [buf][n][k]

    int tid  = threadIdx.x;
    int lane = tid & 31;
    int warp = tid >> 5;
    int wm = warp >> 1;     // 0..3 -> m offset wm*32
    int wn = warp & 1;      // 0..1 -> n offset wn*64
    int bm = blockIdx.x * GBM;
    int bn = blockIdx.y * GBN;

    // A staging coords: 4 float4 per thread per iter
    int arow = tid >> 3;          // row pairs via +0? rows: idx>>3 over idx=tid+i*256
    int ac4  = tid & 7;
    // B staging coords: 2 uint4 per thread per iter
    int brow = tid >> 2;
    int bseg = tid & 3;

    float4 aR[4];
    uint4  bR[2];
    float acc[2][8][4];
    #pragma unroll
    for (int mf = 0; mf < 2; mf++)
        #pragma unroll
        for (int nf = 0; nf < 8; nf++)
            #pragma unroll
            for (int i = 0; i < 4; i++) acc[mf][nf][i] = 0.f;

    // ---- helpers ----
    #define LOADCH(k0)                                                            \
        do {                                                                      \
            _Pragma("unroll")                                                     \
            for (int i = 0; i < 4; i++) {                                         \
                int row = arow + i * 32;                                          \
                aR[i] = *reinterpret_cast<const float4*>(                         \
                    g_U + (size_t)(bm + row) * K_DIM + (k0) + ac4 * 4);           \
            }                                                                     \
            _Pragma("unroll")                                                     \
            for (int i = 0; i < 2; i++) {                                         \
                int row = brow + i * 64;                                          \
                bR[i] = *reinterpret_cast<const uint4*>(                          \
                    Bt + (size_t)(bn + row) * K_DIM + (k0) + bseg * 8);           \
            }                                                                     \
        } while (0)

    #define STORECH(buf)                                                          \
        do {                                                                      \
            _Pragma("unroll")                                                     \
            for (int i = 0; i < 4; i++) {                                         \
                int row = arow + i * 32;                                          \
                __half2 p0 = __floats2half2_rn(aR[i].x, aR[i].y);                 \
                __half2 p1 = __floats2half2_rn(aR[i].z, aR[i].w);                 \
                __half2* d = reinterpret_cast<__half2*>(&As[buf][row][ac4 * 4]);  \
                d[0] = p0; d[1] = p1;                                             \
            }                                                                     \
            _Pragma("unroll")                                                     \
            for (int i = 0; i < 2; i++) {                                         \
                int row = brow + i * 64;                                          \
                *reinterpret_cast<uint4*>(&Bs[buf][row][bseg * 8]) = bR[i];       \
            }                                                                     \
        } while (0)

    // prologue
    LOADCH(0);
    STORECH(0);
    LOADCH(GBK);
    __syncthreads();

    const int NITER = K_DIM / GBK;   // 32
    for (int it = 0; it < NITER; ++it) {
        int cur = it & 1;

        #pragma unroll
        for (int ks = 0; ks < 2; ks++) {          // two k16 steps per BK=32
            uint32_t afr[2][4], bfr[8][2];
            int ar_ = wm * 32 + (lane >> 2);
            int ak_ = ks * 16 + (lane & 3) * 2;
            #pragma unroll
            for (int mf = 0; mf < 2; mf++) {
                const __half* p = &As[cur][ar_ + mf * 16][ak_];
                afr[mf][0] = *reinterpret_cast<const uint32_t*>(p);
                afr[mf][1] = *reinterpret_cast<const uint32_t*>(p + 8 * ASTR);
                afr[mf][2] = *reinterpret_cast<const uint32_t*>(p + 8);
                afr[mf][3] = *reinterpret_cast<const uint32_t*>(p + 8 * ASTR + 8);
            }
            int bn_ = wn * 64 + (lane >> 2);
            #pragma unroll
            for (int nf = 0; nf < 8; nf++) {
                const __half* p = &Bs[cur][bn_ + nf * 8][ak_];
                bfr[nf][0] = *reinterpret_cast<const uint32_t*>(p);
                bfr[nf][1] = *reinterpret_cast<const uint32_t*>(p + 8);
            }
            #pragma unroll
            for (int mf = 0; mf < 2; mf++)
                #pragma unroll
                for (int nf = 0; nf < 8; nf++)
                    asm volatile(
                        "mma.sync.aligned.m16n8k16.row.col.f32.f16.f16.f32 "
                        "{%0,%1,%2,%3}, {%4,%5,%6,%7}, {%8,%9}, {%0,%1,%2,%3};"
                        : "+f"(acc[mf][nf][0]), "+f"(acc[mf][nf][1]),
                          "+f"(acc[mf][nf][2]), "+f"(acc[mf][nf][3])
                        : "r"(afr[mf][0]), "r"(afr[mf][1]),
                          "r"(afr[mf][2]), "r"(afr[mf][3]),
                          "r"(bfr[nf][0]), "r"(bfr[nf][1]));
        }

        if (it + 1 < NITER) {
            STORECH((it + 1) & 1);
            if (it + 2 < NITER) LOADCH((it + 2) * GBK);
        }
        __syncthreads();
    }

    // epilogue: + bias, relu  (D frag: rows lane/4, lane/4+8; cols (lane%4)*2+{0,1})
    #pragma unroll
    for (int mf = 0; mf < 2; mf++) {
        int row0 = bm + wm * 32 + mf * 16 + (lane >> 2);
        #pragma unroll
        for (int nf = 0; nf < 8; nf++) {
            int col = bn + wn * 64 + nf * 8 + (lane & 3) * 2;
            float b0 = __ldg(bias + col);
            float b1 = __ldg(bias + col + 1);
            if (row0 < M) {
                float2 o;
                o.x = fmaxf(acc[mf][nf][0] + b0, 0.f);
                o.y = fmaxf(acc[mf][nf][1] + b1, 0.f);
                *reinterpret_cast<float2*>(out + (size_t)row0 * OUT_DIM + col) = o;
            }
            if (row0 + 8 < M) {
                float2 o;
                o.x = fmaxf(acc[mf][nf][2] + b0, 0.f);
                o.y = fmaxf(acc[mf][nf][3] + b1, 0.f);
                *reinterpret_cast<float2*>(out + (size_t)(row0 + 8) * OUT_DIM + col) = o;
            }
        }
    }
}

// ---------------------------------------------------------------------------
extern "C" void kernel_launch(void* const* d_in, const int* in_sizes, int n_in,
                              void* d_out, int out_size) {
    const float* h      = (const float*)d_in[0];
    const float* basis  = (const float*)d_in[1];
    const float* w_comp = (const float*)d_in[2];
    const float* bias   = (const float*)d_in[3];
    const int*   src    = (const int*)d_in[4];
    const int*   dst    = (const int*)d_in[5];
    const int*   etype  = (const int*)d_in[6];
    float* out = (float*)d_out;

    int N = in_sizes[0] / IN_DIM;   // 20000
    int E = in_sizes[4];            // 320000

    // launch order tuned so ncu (-s 5 -c 1) captures the GEMM (launch #6)
    void* uptr = nullptr;
    cudaGetSymbolAddress(&uptr, g_U);
    cudaMemsetAsync(uptr, 0, (size_t)M_PAD * K_DIM * sizeof(float), 0);   // 1

    fold_kernel<<<(N * 32 + 255) / 256, 256>>>(h, w_comp, N);             // 2

    transpose_kernel<<<dim3(32, 8), dim3(32, 8)>>>(basis);                // 3

    scatter_kernel<<<(E * 32 + 255) / 256, 256>>>(src, dst, etype, E);    // 4

    noop_kernel<<<1, 32>>>();                                             // 5

    __half* btp = nullptr;
    cudaGetSymbolAddress((void**)&btp, g_Bt);
    dim3 grid((M_PAD) / GBM, OUT_DIM / GBN);   // 157 x 2
    gemm_tc_kernel<<<grid, 256>>>(btp, bias, out, N);                     // 6
}